// round 7
// baseline (speedup 1.0000x reference)
#include <cuda_runtime.h>
#include <cstdint>

// Problem constants
#define BB 64
#define CC 64
#define TT 2000
#define PL 200
#define STRD 100
#define EE 512
#define PP 19
#define NROWS (BB*CC*PP)   // 77824
#define EPSV 1e-5f

// GEMM tiling
#define BM 128
#define BN 128
#define BK 40
#define NKG 5                    // 5 k8-groups per stage
#define NSTAGE 5                 // 5*40 = 200 exactly
#define TILE_U32 (NKG*128*8)     // 5120 u32 = 20KB per matrix per buffer

// Scratch
__device__ float g_mean[NROWS];
__device__ float g_inv[NROWS];
__device__ float g_wsum[EE];

// ---------------- wsum ----------------
__global__ void wsum_kernel(const float* __restrict__ W) {
    int d = blockIdx.x * blockDim.x + threadIdx.x;
    if (d < EE) {
        const float* wr = W + (size_t)d * PL;
        float s = 0.f;
        #pragma unroll 8
        for (int l = 0; l < PL; ++l) s += wr[l];
        g_wsum[d] = s;
    }
}

// ---------------- stats + patches copy ----------------
__global__ void stats_kernel(const float* __restrict__ x,
                             float* __restrict__ patches,
                             float* __restrict__ mean_out,
                             float* __restrict__ std_out) {
    int warp = (blockIdx.x * blockDim.x + threadIdx.x) >> 5;
    int lane = threadIdx.x & 31;
    if (warp >= NROWS) return;
    int bc = warp / PP;
    int p  = warp % PP;
    const float* src = x + (size_t)bc * TT + p * STRD;
    float* dst = patches + (size_t)warp * PL;

    float s = 0.f, s2 = 0.f;
    #pragma unroll
    for (int i = 0; i < 7; ++i) {
        int l = lane + i * 32;
        if (l < PL) {
            float v = src[l];
            s += v; s2 += v * v;
            dst[l] = v;
        }
    }
    #pragma unroll
    for (int off = 16; off; off >>= 1) {
        s  += __shfl_xor_sync(0xffffffffu, s,  off);
        s2 += __shfl_xor_sync(0xffffffffu, s2, off);
    }
    if (lane == 0) {
        float mean = s * (1.f / PL);
        float var  = (s2 - s * mean) * (1.f / (PL - 1));
        float sd   = sqrtf(fmaxf(var, 0.f));
        mean_out[warp] = mean;
        std_out[warp]  = sd;
        g_mean[warp] = mean;
        g_inv[warp]  = 1.f / (sd + EPSV);
    }
}

// ---------------- tf32 mma.sync helpers ----------------
__device__ __forceinline__ uint32_t f2tf32(float x) {
    uint32_t r;
    asm("cvt.rna.tf32.f32 %0, %1;" : "=r"(r) : "f"(x));
    return r;
}

__device__ __forceinline__ void mma_tf32(float* d, const uint32_t* a,
                                         const uint32_t* b, const float* c) {
    asm volatile(
        "mma.sync.aligned.m16n8k8.row.col.f32.tf32.tf32.f32 "
        "{%0,%1,%2,%3}, {%4,%5,%6,%7}, {%8,%9}, {%10,%11,%12,%13};\n"
        : "=f"(d[0]), "=f"(d[1]), "=f"(d[2]), "=f"(d[3])
        : "r"(a[0]), "r"(a[1]), "r"(a[2]), "r"(a[3]),
          "r"(b[0]), "r"(b[1]),
          "f"(c[0]), "f"(c[1]), "f"(c[2]), "f"(c[3]));
}

// ---------------- GEMM ----------------
// smem layout (u32 units): buf0A [0,5120) buf0B [5120,10240) buf1A [10240,15360) buf1B [15360,20480)
// per (kg,row): 8 u32 at ((kg*128+row)*8), order [k0,k4,k1,k5,k2,k6,k3,k7] (tf32 bits)
__global__ __launch_bounds__(256, 2) void gemm_tc_kernel(
    const float* __restrict__ x, const float* __restrict__ W,
    const float* __restrict__ bias, const float* __restrict__ pos,
    const int* __restrict__ subj, const float* __restrict__ gain,
    float* __restrict__ emb)
{
    extern __shared__ uint32_t sm[];

    const int tid  = threadIdx.x;
    const int wid  = tid >> 5;
    const int lane = tid & 31;
    const int g    = lane >> 2;   // 0..7
    const int tg   = lane & 3;    // 0..3
    const int wm   = wid >> 1;    // 0..3 : 32-row warp tile
    const int wn   = wid & 1;     // 0..1 : 64-col warp tile

    const int row0 = blockIdx.x * BM;
    const int n0   = blockIdx.y * BN;

    // loader: threads 0..127 -> A rows, 128..255 -> B rows
    const int lrow = tid & 127;
    const float* srcp;
    if (tid < 128) {
        int ar = row0 + lrow;
        srcp = x + (size_t)(ar / PP) * TT + (ar % PP) * STRD;
    } else {
        srcp = W + (size_t)(n0 + lrow) * PL;
    }
    uint32_t* mydst0 = sm + ((tid < 128) ? 0 : TILE_U32) + lrow * 8;

    float acc[2][8][4];
    #pragma unroll
    for (int mt = 0; mt < 2; ++mt)
        #pragma unroll
        for (int nt = 0; nt < 8; ++nt)
            #pragma unroll
            for (int q = 0; q < 4; ++q) acc[mt][nt][q] = 0.f;

    float4 v[10];

    // prologue: load + store stage 0
    #pragma unroll
    for (int j = 0; j < 10; ++j) v[j] = *(const float4*)(srcp + j * 4);
    #pragma unroll
    for (int kg = 0; kg < NKG; ++kg) {
        float4 a = v[2 * kg], b = v[2 * kg + 1];
        uint32_t* d0 = mydst0 + kg * 128 * 8;
        *(uint4*)(d0)     = make_uint4(f2tf32(a.x), f2tf32(b.x), f2tf32(a.y), f2tf32(b.y));
        *(uint4*)(d0 + 4) = make_uint4(f2tf32(a.z), f2tf32(b.z), f2tf32(a.w), f2tf32(b.w));
    }
    __syncthreads();

    #pragma unroll 1
    for (int s = 0; s < NSTAGE; ++s) {
        // prefetch next stage into regs
        if (s + 1 < NSTAGE) {
            const float* sp = srcp + (s + 1) * BK;
            #pragma unroll
            for (int j = 0; j < 10; ++j) v[j] = *(const float4*)(sp + j * 4);
        }

        // compute over buf s&1
        const uint32_t* sA = sm + (s & 1) * (2 * TILE_U32);
        const uint32_t* sB = sA + TILE_U32;
        #pragma unroll
        for (int kg = 0; kg < NKG; ++kg) {
            const uint32_t* ab = sA + kg * 128 * 8;
            const uint32_t* bb = sB + kg * 128 * 8;
            uint32_t af[2][4];
            #pragma unroll
            for (int mt = 0; mt < 2; ++mt) {
                int m = wm * 32 + mt * 16 + g;
                uint2 lo = *(const uint2*)(ab + m * 8 + tg * 2);
                uint2 hi = *(const uint2*)(ab + (m + 8) * 8 + tg * 2);
                af[mt][0] = lo.x; af[mt][1] = hi.x;
                af[mt][2] = lo.y; af[mt][3] = hi.y;
            }
            uint32_t bf[8][2];
            #pragma unroll
            for (int nt = 0; nt < 8; ++nt) {
                int n = wn * 64 + nt * 8 + g;
                uint2 bv = *(const uint2*)(bb + n * 8 + tg * 2);
                bf[nt][0] = bv.x; bf[nt][1] = bv.y;
            }
            #pragma unroll
            for (int mt = 0; mt < 2; ++mt)
                #pragma unroll
                for (int nt = 0; nt < 8; ++nt)
                    mma_tf32(acc[mt][nt], af[mt], bf[nt], acc[mt][nt]);
        }

        // store next stage
        if (s + 1 < NSTAGE) {
            uint32_t* dstb = mydst0 + ((s + 1) & 1) * (2 * TILE_U32);
            #pragma unroll
            for (int kg = 0; kg < NKG; ++kg) {
                float4 a = v[2 * kg], b = v[2 * kg + 1];
                uint32_t* d0 = dstb + kg * 128 * 8;
                *(uint4*)(d0)     = make_uint4(f2tf32(a.x), f2tf32(b.x), f2tf32(a.y), f2tf32(b.y));
                *(uint4*)(d0 + 4) = make_uint4(f2tf32(a.z), f2tf32(b.z), f2tf32(a.w), f2tf32(b.w));
            }
            __syncthreads();
        }
    }

    // epilogue
    #pragma unroll
    for (int mt = 0; mt < 2; ++mt) {
        #pragma unroll
        for (int h = 0; h < 2; ++h) {
            int r = row0 + wm * 32 + mt * 16 + g + h * 8;
            float mv = g_mean[r], iv = g_inv[r];
            int rbc = r / PP, rp = r % PP;
            int sid = subj[rbc >> 6];
            const float* gn = gain + (size_t)sid * EE;
            const float* pe = pos + (size_t)rp * EE;
            float* orow = emb + (size_t)r * EE;
            #pragma unroll
            for (int nt = 0; nt < 8; ++nt) {
                int d = n0 + wn * 64 + nt * 8 + 2 * tg;
                float c0 = acc[mt][nt][h * 2 + 0];
                float c1 = acc[mt][nt][h * 2 + 1];
                float v0 = (iv * (c0 - mv * g_wsum[d])     + bias[d]     + pe[d])     * gn[d];
                float v1 = (iv * (c1 - mv * g_wsum[d + 1]) + bias[d + 1] + pe[d + 1]) * gn[d + 1];
                *(float2*)(orow + d) = make_float2(v0, v1);
            }
        }
    }
}

// ---------------- JAX threefry2x32, partitionable mode ----------------
__device__ __forceinline__ void threefry(uint32_t k0, uint32_t k1,
                                         uint32_t x0, uint32_t x1,
                                         uint32_t& o0, uint32_t& o1) {
    uint32_t ks2 = k0 ^ k1 ^ 0x1BD11BDAu;
    x0 += k0; x1 += k1;
#define TF_RND(r) { x0 += x1; x1 = (x1 << r) | (x1 >> (32 - r)); x1 ^= x0; }
    TF_RND(13) TF_RND(15) TF_RND(26) TF_RND(6)  x0 += k1;  x1 += ks2 + 1u;
    TF_RND(17) TF_RND(29) TF_RND(16) TF_RND(24) x0 += ks2; x1 += k0 + 2u;
    TF_RND(13) TF_RND(15) TF_RND(26) TF_RND(6)  x0 += k0;  x1 += k1 + 3u;
    TF_RND(17) TF_RND(29) TF_RND(16) TF_RND(24) x0 += k1;  x1 += ks2 + 4u;
    TF_RND(13) TF_RND(15) TF_RND(26) TF_RND(6)  x0 += ks2; x1 += k0 + 5u;
#undef TF_RND
    o0 = x0; o1 = x1;
}

__device__ __forceinline__ uint32_t prf32(uint32_t k0, uint32_t k1, uint32_t i) {
    uint32_t o0, o1;
    threefry(k0, k1, 0u, i, o0, o1);
    return o0 ^ o1;
}

__device__ __forceinline__ float u01(uint32_t bits) {
    return __uint_as_float((bits >> 9) | 0x3f800000u) - 1.0f;
}

__global__ void mask_kernel(float* __restrict__ mout) {
    int row = blockIdx.x * blockDim.x + threadIdx.x;
    if (row >= BB * CC) return;
    uint32_t k1a, k1b, k2a, k2b;
    threefry(0u, 42u, 0u, 0u, k1a, k1b);
    threefry(0u, 42u, 0u, 1u, k2a, k2b);

    float r0 = u01(prf32(k2a, k2b, (uint32_t)(row * 3 + 0)));
    float r1 = u01(prf32(k2a, k2b, (uint32_t)(row * 3 + 1)));
    float r2 = u01(prf32(k2a, k2b, (uint32_t)(row * 3 + 2)));

    bool m[PP];
    #pragma unroll
    for (int j = 0; j < PP; ++j)
        m[j] = u01(prf32(k1a, k1b, (uint32_t)(row * PP + j))) < 0.1f;

    if (r0 < 0.5f)  { for (int j = PP - 1; j >= 1; --j) m[j] = m[j] | m[j - 1]; }
    if (r1 < 0.5f)  { for (int j = 0; j < PP - 1; ++j) m[j] = m[j] | m[j + 1]; }
    if (r2 < 0.25f) { for (int j = 0; j < PP - 1; ++j) m[j] = m[j] | m[j + 1]; }

    float* dst = mout + (size_t)row * PP;
    #pragma unroll
    for (int j = 0; j < PP; ++j) dst[j] = m[j] ? 1.0f : 0.0f;
}

// ---------------- launch ----------------
extern "C" void kernel_launch(void* const* d_in, const int* in_sizes, int n_in,
                              void* d_out, int out_size) {
    const float* x    = (const float*)d_in[0];
    const int*   subj = (const int*)  d_in[1];
    const float* W    = (const float*)d_in[2];
    const float* bias = (const float*)d_in[3];
    const float* pos  = (const float*)d_in[4];
    const float* gain = (const float*)d_in[5];

    float* out      = (float*)d_out;
    float* emb      = out;                               // 77824*512
    float* patches  = emb + (size_t)NROWS * EE;          // 77824*200
    float* mfloat   = patches + (size_t)NROWS * PL;      // 77824
    float* mean_out = mfloat + NROWS;                    // 77824
    float* std_out  = mean_out + NROWS;                  // 77824

    const int smem_bytes = 4 * TILE_U32 * 4;             // 81920

    static bool attr_set = false;
    if (!attr_set) {
        cudaFuncSetAttribute(gemm_tc_kernel,
                             cudaFuncAttributeMaxDynamicSharedMemorySize, smem_bytes);
        attr_set = true;
    }

    wsum_kernel<<<2, 256>>>(W);
    stats_kernel<<<NROWS / 8, 256>>>(x, patches, mean_out, std_out);
    dim3 g(NROWS / BM, EE / BN);
    gemm_tc_kernel<<<g, 256, smem_bytes>>>(x, W, bias, pos, subj, gain, emb);
    mask_kernel<<<(BB * CC) / 256, 256>>>(mfloat);
}

// round 9
// speedup vs baseline: 1.2303x; 1.2303x over previous
#include <cuda_runtime.h>
#include <cuda_fp16.h>
#include <cstdint>

// Problem constants
#define BB 64
#define CC 64
#define TT 2000
#define PL 200
#define STRD 100
#define EE 512
#define PP 19
#define NROWS (BB*CC*PP)   // 77824
#define EPSV 1e-5f

// GEMM tiling: 128M x 64N per CTA, 8 warps of 32x32, fp16 k16 MMA
#define BM 128
#define BN 64
#define KSTG 32        // floats per stage = 2 kg of 16
#define NSTAGE 7       // 224 padded K (13 real kg)

// Scratch
__device__ float g_mean[NROWS];
__device__ float g_inv[NROWS];
__device__ float g_wsum[EE];

// ---------------- wsum ----------------
__global__ void wsum_kernel(const float* __restrict__ W) {
    int d = blockIdx.x * blockDim.x + threadIdx.x;
    if (d < EE) {
        const float* wr = W + (size_t)d * PL;
        float s = 0.f;
        #pragma unroll 8
        for (int l = 0; l < PL; ++l) s += wr[l];
        g_wsum[d] = s;
    }
}

// ---------------- stats + patches copy ----------------
__global__ void stats_kernel(const float* __restrict__ x,
                             float* __restrict__ patches,
                             float* __restrict__ mean_out,
                             float* __restrict__ std_out) {
    int warp = (blockIdx.x * blockDim.x + threadIdx.x) >> 5;
    int lane = threadIdx.x & 31;
    if (warp >= NROWS) return;
    int bc = warp / PP;
    int p  = warp % PP;
    const float* src = x + (size_t)bc * TT + p * STRD;
    float* dst = patches + (size_t)warp * PL;

    float s = 0.f, s2 = 0.f;
    #pragma unroll
    for (int i = 0; i < 7; ++i) {
        int l = lane + i * 32;
        if (l < PL) {
            float v = src[l];
            s += v; s2 += v * v;
            dst[l] = v;
        }
    }
    #pragma unroll
    for (int off = 16; off; off >>= 1) {
        s  += __shfl_xor_sync(0xffffffffu, s,  off);
        s2 += __shfl_xor_sync(0xffffffffu, s2, off);
    }
    if (lane == 0) {
        float mean = s * (1.f / PL);
        float var  = (s2 - s * mean) * (1.f / (PL - 1));
        float sd   = sqrtf(fmaxf(var, 0.f));
        mean_out[warp] = mean;
        std_out[warp]  = sd;
        g_mean[warp] = mean;
        g_inv[warp]  = 1.f / (sd + EPSV);
    }
}

// ---------------- fp16 mma helpers ----------------
__device__ __forceinline__ uint32_t packh2(float lo, float hi) {
    __half2 h = __floats2half2_rn(lo, hi);
    return *(uint32_t*)&h;
}

__device__ __forceinline__ void mma_f16_k16(float* d, const uint32_t* a,
                                            const uint32_t* b, const float* c) {
    asm volatile(
        "mma.sync.aligned.m16n8k16.row.col.f32.f16.f16.f32 "
        "{%0,%1,%2,%3}, {%4,%5,%6,%7}, {%8,%9}, {%10,%11,%12,%13};\n"
        : "=f"(d[0]), "=f"(d[1]), "=f"(d[2]), "=f"(d[3])
        : "r"(a[0]), "r"(a[1]), "r"(a[2]), "r"(a[3]),
          "r"(b[0]), "r"(b[1]),
          "f"(c[0]), "f"(c[1]), "f"(c[2]), "f"(c[3]));
}

// pair-permuted kg layout: per row per kg, 8 u32 words:
// w0=(h0,h1) w1=(h8,h9) w2=(h2,h3) w3=(h10,h11) w4=(h4,h5) w5=(h12,h13) w6=(h6,h7) w7=(h14,h15)
// fragment (a0,a2) / (b0,b1) = one LDS.64 at word offset 2*tg
__device__ __forceinline__ void permute_store(uint32_t* dst, const float4* v4) {
    const float* f = (const float*)v4;   // 16 floats of one kg
    uint4 lo, hi;
    lo.x = packh2(f[0],  f[1]);  lo.y = packh2(f[8],  f[9]);
    lo.z = packh2(f[2],  f[3]);  lo.w = packh2(f[10], f[11]);
    hi.x = packh2(f[4],  f[5]);  hi.y = packh2(f[12], f[13]);
    hi.z = packh2(f[6],  f[7]);  hi.w = packh2(f[14], f[15]);
    *(uint4*)(dst)     = lo;
    *(uint4*)(dst + 4) = hi;
}

// ---------------- GEMM ----------------
__global__ __launch_bounds__(256, 2) void gemm_tc_kernel(
    const float* __restrict__ x, const float* __restrict__ W,
    const float* __restrict__ bias, const float* __restrict__ pos,
    const int* __restrict__ subj, const float* __restrict__ gain,
    float* __restrict__ emb)
{
    __shared__ uint32_t smA[2 * 128 * 8];
    __shared__ uint32_t smB[2 * 64 * 8];

    const int tid  = threadIdx.x;
    const int wid  = tid >> 5;
    const int lane = tid & 31;
    const int g    = lane >> 2;   // 0..7
    const int tg   = lane & 3;    // 0..3
    const int wm   = wid >> 1;    // 0..3 : 32-row warp tile
    const int wn   = wid & 1;     // 0..1 : 32-col warp tile

    const int row0 = blockIdx.x * BM;
    const int n0   = blockIdx.y * BN;

    // loaders:
    //  t <128 : A row t, 32 floats/stage (2 kg)
    //  t>=128 : B row (t-128)>>1, kg half (t&1), 16 floats/stage
    const bool isA = (tid < 128);
    const int arow = tid & 127;
    const int brow = (tid - 128) >> 1;
    const int bkg  = tid & 1;
    const int kofs = isA ? 0 : bkg * 16;   // extra k offset baked into srcp
    const float* srcp;
    if (isA) {
        int ar = row0 + arow;
        srcp = x + (size_t)(ar / PP) * TT + (ar % PP) * STRD;
    } else {
        srcp = W + (size_t)(n0 + brow) * PL + kofs;
    }

    float acc[2][4][4];
    #pragma unroll
    for (int mt = 0; mt < 2; ++mt)
        #pragma unroll
        for (int nt = 0; nt < 4; ++nt)
            #pragma unroll
            for (int q = 0; q < 4; ++q) acc[mt][nt][q] = 0.f;

    float4 v[8];
    const int nload = isA ? 8 : 4;

    // prefetch stage 0
    #pragma unroll
    for (int j = 0; j < 8; ++j) {
        if (j < nload) {
            int k = kofs + j * 4;   // true k index
            v[j] = (k < PL) ? *(const float4*)(srcp + j * 4)
                            : make_float4(0.f, 0.f, 0.f, 0.f);
        }
    }

    #pragma unroll 1
    for (int s = 0; s < NSTAGE; ++s) {
        __syncthreads();
        // store current stage
        if (isA) {
            permute_store(&smA[0 * 1024 + arow * 8], &v[0]);
            permute_store(&smA[1 * 1024 + arow * 8], &v[4]);
        } else {
            permute_store(&smB[bkg * 512 + brow * 8], &v[0]);
        }
        __syncthreads();

        // prefetch next stage (srcp-relative offset; kofs only for validity)
        if (s + 1 < NSTAGE) {
            const int kb = (s + 1) * KSTG;
            #pragma unroll
            for (int j = 0; j < 8; ++j) {
                if (j < nload) {
                    int rel = kb + j * 4;
                    int k = kofs + rel;   // true k index
                    v[j] = (k < PL) ? *(const float4*)(srcp + rel)
                                    : make_float4(0.f, 0.f, 0.f, 0.f);
                }
            }
        }

        // compute: kg pair (skip the all-zero kg 13 at s==6)
        #pragma unroll
        for (int kg = 0; kg < 2; ++kg) {
            if (s == NSTAGE - 1 && kg == 1) break;
            const uint32_t* ab = smA + kg * 1024;
            const uint32_t* bb = smB + kg * 512;
            uint32_t af[2][4];
            #pragma unroll
            for (int mt = 0; mt < 2; ++mt) {
                int m = wm * 32 + mt * 16 + g;
                uint2 lo = *(const uint2*)(ab + m * 8 + tg * 2);
                uint2 hi = *(const uint2*)(ab + (m + 8) * 8 + tg * 2);
                af[mt][0] = lo.x; af[mt][1] = hi.x;
                af[mt][2] = lo.y; af[mt][3] = hi.y;
            }
            uint32_t bf[4][2];
            #pragma unroll
            for (int nt = 0; nt < 4; ++nt) {
                int n = wn * 32 + nt * 8 + g;
                uint2 bv = *(const uint2*)(bb + n * 8 + tg * 2);
                bf[nt][0] = bv.x; bf[nt][1] = bv.y;
            }
            #pragma unroll
            for (int mt = 0; mt < 2; ++mt)
                #pragma unroll
                for (int nt = 0; nt < 4; ++nt)
                    mma_f16_k16(acc[mt][nt], af[mt], bf[nt], acc[mt][nt]);
        }
    }

    // epilogue
    #pragma unroll
    for (int mt = 0; mt < 2; ++mt) {
        #pragma unroll
        for (int h = 0; h < 2; ++h) {
            int r = row0 + wm * 32 + mt * 16 + g + h * 8;
            float mv = g_mean[r], iv = g_inv[r];
            int rbc = r / PP, rp = r % PP;
            int sid = subj[rbc >> 6];
            const float* gn = gain + (size_t)sid * EE;
            const float* pe = pos + (size_t)rp * EE;
            float* orow = emb + (size_t)r * EE;
            #pragma unroll
            for (int nt = 0; nt < 4; ++nt) {
                int d = n0 + wn * 32 + nt * 8 + 2 * tg;
                float c0 = acc[mt][nt][h * 2 + 0];
                float c1 = acc[mt][nt][h * 2 + 1];
                float v0 = (iv * (c0 - mv * g_wsum[d])     + bias[d]     + pe[d])     * gn[d];
                float v1 = (iv * (c1 - mv * g_wsum[d + 1]) + bias[d + 1] + pe[d + 1]) * gn[d + 1];
                *(float2*)(orow + d) = make_float2(v0, v1);
            }
        }
    }
}

// ---------------- JAX threefry2x32, partitionable mode ----------------
__device__ __forceinline__ void threefry(uint32_t k0, uint32_t k1,
                                         uint32_t x0, uint32_t x1,
                                         uint32_t& o0, uint32_t& o1) {
    uint32_t ks2 = k0 ^ k1 ^ 0x1BD11BDAu;
    x0 += k0; x1 += k1;
#define TF_RND(r) { x0 += x1; x1 = (x1 << r) | (x1 >> (32 - r)); x1 ^= x0; }
    TF_RND(13) TF_RND(15) TF_RND(26) TF_RND(6)  x0 += k1;  x1 += ks2 + 1u;
    TF_RND(17) TF_RND(29) TF_RND(16) TF_RND(24) x0 += ks2; x1 += k0 + 2u;
    TF_RND(13) TF_RND(15) TF_RND(26) TF_RND(6)  x0 += k0;  x1 += k1 + 3u;
    TF_RND(17) TF_RND(29) TF_RND(16) TF_RND(24) x0 += k1;  x1 += ks2 + 4u;
    TF_RND(13) TF_RND(15) TF_RND(26) TF_RND(6)  x0 += ks2; x1 += k0 + 5u;
#undef TF_RND
    o0 = x0; o1 = x1;
}

__device__ __forceinline__ uint32_t prf32(uint32_t k0, uint32_t k1, uint32_t i) {
    uint32_t o0, o1;
    threefry(k0, k1, 0u, i, o0, o1);
    return o0 ^ o1;
}

__device__ __forceinline__ float u01(uint32_t bits) {
    return __uint_as_float((bits >> 9) | 0x3f800000u) - 1.0f;
}

__global__ void mask_kernel(float* __restrict__ mout) {
    int row = blockIdx.x * blockDim.x + threadIdx.x;
    if (row >= BB * CC) return;
    uint32_t k1a, k1b, k2a, k2b;
    threefry(0u, 42u, 0u, 0u, k1a, k1b);
    threefry(0u, 42u, 0u, 1u, k2a, k2b);

    float r0 = u01(prf32(k2a, k2b, (uint32_t)(row * 3 + 0)));
    float r1 = u01(prf32(k2a, k2b, (uint32_t)(row * 3 + 1)));
    float r2 = u01(prf32(k2a, k2b, (uint32_t)(row * 3 + 2)));

    bool m[PP];
    #pragma unroll
    for (int j = 0; j < PP; ++j)
        m[j] = u01(prf32(k1a, k1b, (uint32_t)(row * PP + j))) < 0.1f;

    if (r0 < 0.5f)  { for (int j = PP - 1; j >= 1; --j) m[j] = m[j] | m[j - 1]; }
    if (r1 < 0.5f)  { for (int j = 0; j < PP - 1; ++j) m[j] = m[j] | m[j + 1]; }
    if (r2 < 0.25f) { for (int j = 0; j < PP - 1; ++j) m[j] = m[j] | m[j + 1]; }

    float* dst = mout + (size_t)row * PP;
    #pragma unroll
    for (int j = 0; j < PP; ++j) dst[j] = m[j] ? 1.0f : 0.0f;
}

// ---------------- launch ----------------
extern "C" void kernel_launch(void* const* d_in, const int* in_sizes, int n_in,
                              void* d_out, int out_size) {
    const float* x    = (const float*)d_in[0];
    const int*   subj = (const int*)  d_in[1];
    const float* W    = (const float*)d_in[2];
    const float* bias = (const float*)d_in[3];
    const float* pos  = (const float*)d_in[4];
    const float* gain = (const float*)d_in[5];

    float* out      = (float*)d_out;
    float* emb      = out;                               // 77824*512
    float* patches  = emb + (size_t)NROWS * EE;          // 77824*200
    float* mfloat   = patches + (size_t)NROWS * PL;      // 77824
    float* mean_out = mfloat + NROWS;                    // 77824
    float* std_out  = mean_out + NROWS;                  // 77824

    wsum_kernel<<<2, 256>>>(W);
    stats_kernel<<<NROWS / 8, 256>>>(x, patches, mean_out, std_out);
    mask_kernel<<<(BB * CC) / 256, 256>>>(mfloat);
    dim3 g(NROWS / BM, EE / BN);
    gemm_tc_kernel<<<g, 256>>>(x, W, bias, pos, subj, gain, emb);
}

// round 10
// speedup vs baseline: 1.3503x; 1.0976x over previous
#include <cuda_runtime.h>
#include <cuda_fp16.h>
#include <cstdint>

// Problem constants
#define BB 64
#define CC 64
#define TT 2000
#define PL 200
#define STRD 100
#define EE 512
#define PP 19
#define NROWS (BB*CC*PP)   // 77824
#define EPSV 1e-5f

// GEMM tiling: 128M x 64N per CTA, 8 warps of 32x32, fp16 k16 MMA
#define BM 128
#define BN 64
#define KSTG 32        // floats per stage = 2 kg of 16
#define NSTAGE 7       // 224 padded K (13 real kg)

// Scratch
__device__ float g_mean[NROWS];
__device__ float g_inv[NROWS];
__device__ float g_wsum[EE];
__device__ float g_pe2[PP * EE];   // bias[d] + pos[p][d]

// ---------------- wsum ----------------
__global__ void wsum_kernel(const float* __restrict__ W) {
    int d = blockIdx.x * blockDim.x + threadIdx.x;
    if (d < EE) {
        const float* wr = W + (size_t)d * PL;
        float s = 0.f;
        #pragma unroll 8
        for (int l = 0; l < PL; ++l) s += wr[l];
        g_wsum[d] = s;
    }
}

// ---------------- pe2 = bias + pos ----------------
__global__ void pe2_kernel(const float* __restrict__ bias, const float* __restrict__ pos) {
    int i = blockIdx.x * blockDim.x + threadIdx.x;   // 0 .. PP*EE-1
    if (i < PP * EE) g_pe2[i] = pos[i] + bias[i & (EE - 1)];
}

// ---------------- stats + patches copy ----------------
__global__ void stats_kernel(const float* __restrict__ x,
                             float* __restrict__ patches,
                             float* __restrict__ mean_out,
                             float* __restrict__ std_out) {
    int warp = (blockIdx.x * blockDim.x + threadIdx.x) >> 5;
    int lane = threadIdx.x & 31;
    if (warp >= NROWS) return;
    int bc = warp / PP;
    int p  = warp % PP;
    const float* src = x + (size_t)bc * TT + p * STRD;
    float* dst = patches + (size_t)warp * PL;

    float s = 0.f, s2 = 0.f;
    #pragma unroll
    for (int i = 0; i < 7; ++i) {
        int l = lane + i * 32;
        if (l < PL) {
            float v = src[l];
            s += v; s2 += v * v;
            dst[l] = v;
        }
    }
    #pragma unroll
    for (int off = 16; off; off >>= 1) {
        s  += __shfl_xor_sync(0xffffffffu, s,  off);
        s2 += __shfl_xor_sync(0xffffffffu, s2, off);
    }
    if (lane == 0) {
        float mean = s * (1.f / PL);
        float var  = (s2 - s * mean) * (1.f / (PL - 1));
        float sd   = sqrtf(fmaxf(var, 0.f));
        mean_out[warp] = mean;
        std_out[warp]  = sd;
        g_mean[warp] = mean;
        g_inv[warp]  = 1.f / (sd + EPSV);
    }
}

// ---------------- fp16 mma helpers ----------------
__device__ __forceinline__ uint32_t packh2(float lo, float hi) {
    __half2 h = __floats2half2_rn(lo, hi);
    return *(uint32_t*)&h;
}

__device__ __forceinline__ void mma_f16_k16(float* d, const uint32_t* a,
                                            const uint32_t* b, const float* c) {
    asm volatile(
        "mma.sync.aligned.m16n8k16.row.col.f32.f16.f16.f32 "
        "{%0,%1,%2,%3}, {%4,%5,%6,%7}, {%8,%9}, {%10,%11,%12,%13};\n"
        : "=f"(d[0]), "=f"(d[1]), "=f"(d[2]), "=f"(d[3])
        : "r"(a[0]), "r"(a[1]), "r"(a[2]), "r"(a[3]),
          "r"(b[0]), "r"(b[1]),
          "f"(c[0]), "f"(c[1]), "f"(c[2]), "f"(c[3]));
}

// pair-permuted kg layout: per row per kg, 8 u32 words:
// w0=(h0,h1) w1=(h8,h9) w2=(h2,h3) w3=(h10,h11) w4=(h4,h5) w5=(h12,h13) w6=(h6,h7) w7=(h14,h15)
__device__ __forceinline__ void permute_store(uint32_t* dst, const float4* v4) {
    const float* f = (const float*)v4;   // 16 floats of one kg
    uint4 lo, hi;
    lo.x = packh2(f[0],  f[1]);  lo.y = packh2(f[8],  f[9]);
    lo.z = packh2(f[2],  f[3]);  lo.w = packh2(f[10], f[11]);
    hi.x = packh2(f[4],  f[5]);  hi.y = packh2(f[12], f[13]);
    hi.z = packh2(f[6],  f[7]);  hi.w = packh2(f[14], f[15]);
    *(uint4*)(dst)     = lo;
    *(uint4*)(dst + 4) = hi;
}

// ---------------- GEMM ----------------
__global__ __launch_bounds__(256, 2) void gemm_tc_kernel(
    const float* __restrict__ x, const float* __restrict__ W,
    const int* __restrict__ subj, const float* __restrict__ gain,
    float* __restrict__ emb)
{
    __shared__ uint32_t smA[2 * 128 * 8];
    __shared__ uint32_t smB[2 * 64 * 8];

    const int tid  = threadIdx.x;
    const int wid  = tid >> 5;
    const int lane = tid & 31;
    const int g    = lane >> 2;   // 0..7
    const int tg   = lane & 3;    // 0..3
    const int wm   = wid >> 1;    // 0..3 : 32-row warp tile
    const int wn   = wid & 1;     // 0..1 : 32-col warp tile

    const int row0 = blockIdx.x * BM;
    const int n0   = blockIdx.y * BN;

    // A loader: all 256 threads, 2 per row: row=tid>>1, kg half = tid&1 (16 floats)
    const int arow = tid >> 1;
    const int akg  = tid & 1;
    const int akofs = akg * 16;
    const float* srcA;
    {
        int ar = row0 + arow;
        srcA = x + (size_t)(ar / PP) * TT + (ar % PP) * STRD + akofs;
    }
    // B loader: all 256 threads, 4 per row: row=tid>>2, q=tid&3 -> kg=q>>1, c8=(q&1)*8
    const int brow = tid >> 2;
    const int bq   = tid & 3;
    const int bkg  = bq >> 1;
    const int bc8  = (bq & 1) * 8;
    const int bkofs = bkg * 16 + bc8;
    const float* srcB = W + (size_t)(n0 + brow) * PL + bkofs;

    float acc[2][4][4];
    #pragma unroll
    for (int mt = 0; mt < 2; ++mt)
        #pragma unroll
        for (int nt = 0; nt < 4; ++nt)
            #pragma unroll
            for (int q = 0; q < 4; ++q) acc[mt][nt][q] = 0.f;

    float4 va[4];
    float4 vb[2];

    // prefetch stage 0
    #pragma unroll
    for (int j = 0; j < 4; ++j) {
        int k = akofs + j * 4;
        va[j] = (k < PL) ? *(const float4*)(srcA + j * 4)
                         : make_float4(0.f, 0.f, 0.f, 0.f);
    }
    #pragma unroll
    for (int j = 0; j < 2; ++j) {
        int k = bkofs + j * 4;
        vb[j] = (k < PL) ? *(const float4*)(srcB + j * 4)
                         : make_float4(0.f, 0.f, 0.f, 0.f);
    }

    #pragma unroll 1
    for (int s = 0; s < NSTAGE; ++s) {
        __syncthreads();
        // store current stage
        permute_store(&smA[akg * 1024 + arow * 8], va);
        {
            const float* f = (const float*)vb;   // 8 floats, k = bkg*16+bc8 ..+7
            uint32_t w0 = packh2(f[0], f[1]);
            uint32_t w1 = packh2(f[2], f[3]);
            uint32_t w2 = packh2(f[4], f[5]);
            uint32_t w3 = packh2(f[6], f[7]);
            uint32_t* db = &smB[bkg * 512 + brow * 8 + (bc8 ? 1 : 0)];
            db[0] = w0; db[2] = w1; db[4] = w2; db[6] = w3;
        }
        __syncthreads();

        // prefetch next stage
        if (s + 1 < NSTAGE) {
            const int kb = (s + 1) * KSTG;
            #pragma unroll
            for (int j = 0; j < 4; ++j) {
                int rel = kb + j * 4;
                int k = akofs + rel;
                va[j] = (k < PL) ? *(const float4*)(srcA + rel)
                                 : make_float4(0.f, 0.f, 0.f, 0.f);
            }
            #pragma unroll
            for (int j = 0; j < 2; ++j) {
                int rel = kb + j * 4;
                int k = bkofs + rel;
                vb[j] = (k < PL) ? *(const float4*)(srcB + rel)
                                 : make_float4(0.f, 0.f, 0.f, 0.f);
            }
        }

        // compute: kg pair (skip the all-zero kg 13 at s==6)
        #pragma unroll
        for (int kg = 0; kg < 2; ++kg) {
            if (s == NSTAGE - 1 && kg == 1) break;
            const uint32_t* ab = smA + kg * 1024;
            const uint32_t* bb = smB + kg * 512;
            uint32_t af[2][4];
            #pragma unroll
            for (int mt = 0; mt < 2; ++mt) {
                int m = wm * 32 + mt * 16 + g;
                uint2 lo = *(const uint2*)(ab + m * 8 + tg * 2);
                uint2 hi = *(const uint2*)(ab + (m + 8) * 8 + tg * 2);
                af[mt][0] = lo.x; af[mt][1] = hi.x;
                af[mt][2] = lo.y; af[mt][3] = hi.y;
            }
            uint32_t bf[4][2];
            #pragma unroll
            for (int nt = 0; nt < 4; ++nt) {
                int n = wn * 32 + nt * 8 + g;
                uint2 bv = *(const uint2*)(bb + n * 8 + tg * 2);
                bf[nt][0] = bv.x; bf[nt][1] = bv.y;
            }
            #pragma unroll
            for (int mt = 0; mt < 2; ++mt)
                #pragma unroll
                for (int nt = 0; nt < 4; ++nt)
                    mma_f16_k16(acc[mt][nt], af[mt], bf[nt], acc[mt][nt]);
        }
    }

    // epilogue: hoisted invariants + float2 loads
    const int dbase = n0 + wn * 32 + 2 * tg;
    float2 ws[4];
    #pragma unroll
    for (int nt = 0; nt < 4; ++nt)
        ws[nt] = *(const float2*)&g_wsum[dbase + nt * 8];

    #pragma unroll
    for (int mt = 0; mt < 2; ++mt) {
        #pragma unroll
        for (int h = 0; h < 2; ++h) {
            int r = row0 + wm * 32 + mt * 16 + g + h * 8;
            float mv = g_mean[r], iv = g_inv[r];
            int rp = r % PP;
            int sid = subj[(r / PP) >> 6];
            const float* gnrow = gain + (size_t)sid * EE;
            const float* perow = g_pe2 + (size_t)rp * EE;
            float* orow = emb + (size_t)r * EE;
            float miv = mv * iv;
            #pragma unroll
            for (int nt = 0; nt < 4; ++nt) {
                int d = dbase + nt * 8;
                float2 pv = *(const float2*)&perow[d];
                float2 gv = *(const float2*)&gnrow[d];
                float c0 = acc[mt][nt][h * 2 + 0];
                float c1 = acc[mt][nt][h * 2 + 1];
                float v0 = (iv * c0 - miv * ws[nt].x + pv.x) * gv.x;
                float v1 = (iv * c1 - miv * ws[nt].y + pv.y) * gv.y;
                *(float2*)&orow[d] = make_float2(v0, v1);
            }
        }
    }
}

// ---------------- JAX threefry2x32, partitionable mode ----------------
__device__ __forceinline__ void threefry(uint32_t k0, uint32_t k1,
                                         uint32_t x0, uint32_t x1,
                                         uint32_t& o0, uint32_t& o1) {
    uint32_t ks2 = k0 ^ k1 ^ 0x1BD11BDAu;
    x0 += k0; x1 += k1;
#define TF_RND(r) { x0 += x1; x1 = (x1 << r) | (x1 >> (32 - r)); x1 ^= x0; }
    TF_RND(13) TF_RND(15) TF_RND(26) TF_RND(6)  x0 += k1;  x1 += ks2 + 1u;
    TF_RND(17) TF_RND(29) TF_RND(16) TF_RND(24) x0 += ks2; x1 += k0 + 2u;
    TF_RND(13) TF_RND(15) TF_RND(26) TF_RND(6)  x0 += k0;  x1 += k1 + 3u;
    TF_RND(17) TF_RND(29) TF_RND(16) TF_RND(24) x0 += k1;  x1 += ks2 + 4u;
    TF_RND(13) TF_RND(15) TF_RND(26) TF_RND(6)  x0 += ks2; x1 += k0 + 5u;
#undef TF_RND
    o0 = x0; o1 = x1;
}

__device__ __forceinline__ uint32_t prf32(uint32_t k0, uint32_t k1, uint32_t i) {
    uint32_t o0, o1;
    threefry(k0, k1, 0u, i, o0, o1);
    return o0 ^ o1;
}

__device__ __forceinline__ float u01(uint32_t bits) {
    return __uint_as_float((bits >> 9) | 0x3f800000u) - 1.0f;
}

__global__ void mask_kernel(float* __restrict__ mout) {
    int row = blockIdx.x * blockDim.x + threadIdx.x;
    if (row >= BB * CC) return;
    uint32_t k1a, k1b, k2a, k2b;
    threefry(0u, 42u, 0u, 0u, k1a, k1b);
    threefry(0u, 42u, 0u, 1u, k2a, k2b);

    float r0 = u01(prf32(k2a, k2b, (uint32_t)(row * 3 + 0)));
    float r1 = u01(prf32(k2a, k2b, (uint32_t)(row * 3 + 1)));
    float r2 = u01(prf32(k2a, k2b, (uint32_t)(row * 3 + 2)));

    bool m[PP];
    #pragma unroll
    for (int j = 0; j < PP; ++j)
        m[j] = u01(prf32(k1a, k1b, (uint32_t)(row * PP + j))) < 0.1f;

    if (r0 < 0.5f)  { for (int j = PP - 1; j >= 1; --j) m[j] = m[j] | m[j - 1]; }
    if (r1 < 0.5f)  { for (int j = 0; j < PP - 1; ++j) m[j] = m[j] | m[j + 1]; }
    if (r2 < 0.25f) { for (int j = 0; j < PP - 1; ++j) m[j] = m[j] | m[j + 1]; }

    float* dst = mout + (size_t)row * PP;
    #pragma unroll
    for (int j = 0; j < PP; ++j) dst[j] = m[j] ? 1.0f : 0.0f;
}

// ---------------- launch ----------------
extern "C" void kernel_launch(void* const* d_in, const int* in_sizes, int n_in,
                              void* d_out, int out_size) {
    const float* x    = (const float*)d_in[0];
    const int*   subj = (const int*)  d_in[1];
    const float* W    = (const float*)d_in[2];
    const float* bias = (const float*)d_in[3];
    const float* pos  = (const float*)d_in[4];
    const float* gain = (const float*)d_in[5];

    float* out      = (float*)d_out;
    float* emb      = out;                               // 77824*512
    float* patches  = emb + (size_t)NROWS * EE;          // 77824*200
    float* mfloat   = patches + (size_t)NROWS * PL;      // 77824
    float* mean_out = mfloat + NROWS;                    // 77824
    float* std_out  = mean_out + NROWS;                  // 77824

    wsum_kernel<<<2, 256>>>(W);
    pe2_kernel<<<(PP * EE) / 256, 256>>>(bias, pos);
    stats_kernel<<<NROWS / 8, 256>>>(x, patches, mean_out, std_out);
    mask_kernel<<<(BB * CC) / 256, 256>>>(mfloat);
    dim3 g(NROWS / BM, EE / BN);
    gemm_tc_kernel<<<g, 256>>>(x, W, subj, gain, emb);
}

// round 11
// speedup vs baseline: 1.4021x; 1.0384x over previous
#include <cuda_runtime.h>
#include <cuda_fp16.h>
#include <cstdint>

// Problem constants
#define BB 64
#define CC 64
#define TT 2000
#define PL 200
#define STRD 100
#define EE 512
#define PP 19
#define NROWS (BB*CC*PP)   // 77824
#define EPSV 1e-5f

// GEMM tiling: 128M x 128N per CTA, 16 warps of 32x32, fp16 k16 MMA
#define BM 128
#define BN 128
#define KSTG 32        // floats per stage = 2 kg of 16
#define NSTAGE 7       // 224 padded K (13 real kg)

// Scratch
__device__ float g_mean[NROWS];
__device__ float g_inv[NROWS];
__device__ float g_wsum[EE];
__device__ float g_pe2[PP * EE];   // bias[d] + pos[p][d]

// ---------------- wsum ----------------
__global__ void wsum_kernel(const float* __restrict__ W) {
    int d = blockIdx.x * blockDim.x + threadIdx.x;
    if (d < EE) {
        const float* wr = W + (size_t)d * PL;
        float s = 0.f;
        #pragma unroll 8
        for (int l = 0; l < PL; ++l) s += wr[l];
        g_wsum[d] = s;
    }
}

// ---------------- pe2 = bias + pos ----------------
__global__ void pe2_kernel(const float* __restrict__ bias, const float* __restrict__ pos) {
    int i = blockIdx.x * blockDim.x + threadIdx.x;   // 0 .. PP*EE-1
    if (i < PP * EE) g_pe2[i] = pos[i] + bias[i & (EE - 1)];
}

// ---------------- stats + patches copy ----------------
__global__ void stats_kernel(const float* __restrict__ x,
                             float* __restrict__ patches,
                             float* __restrict__ mean_out,
                             float* __restrict__ std_out) {
    int warp = (blockIdx.x * blockDim.x + threadIdx.x) >> 5;
    int lane = threadIdx.x & 31;
    if (warp >= NROWS) return;
    int bc = warp / PP;
    int p  = warp % PP;
    const float* src = x + (size_t)bc * TT + p * STRD;
    float* dst = patches + (size_t)warp * PL;

    float s = 0.f, s2 = 0.f;
    #pragma unroll
    for (int i = 0; i < 7; ++i) {
        int l = lane + i * 32;
        if (l < PL) {
            float v = src[l];
            s += v; s2 += v * v;
            dst[l] = v;
        }
    }
    #pragma unroll
    for (int off = 16; off; off >>= 1) {
        s  += __shfl_xor_sync(0xffffffffu, s,  off);
        s2 += __shfl_xor_sync(0xffffffffu, s2, off);
    }
    if (lane == 0) {
        float mean = s * (1.f / PL);
        float var  = (s2 - s * mean) * (1.f / (PL - 1));
        float sd   = sqrtf(fmaxf(var, 0.f));
        mean_out[warp] = mean;
        std_out[warp]  = sd;
        g_mean[warp] = mean;
        g_inv[warp]  = 1.f / (sd + EPSV);
    }
}

// ---------------- fp16 mma helpers ----------------
__device__ __forceinline__ uint32_t packh2(float lo, float hi) {
    __half2 h = __floats2half2_rn(lo, hi);
    return *(uint32_t*)&h;
}

__device__ __forceinline__ void mma_f16_k16(float* d, const uint32_t* a,
                                            const uint32_t* b, const float* c) {
    asm volatile(
        "mma.sync.aligned.m16n8k16.row.col.f32.f16.f16.f32 "
        "{%0,%1,%2,%3}, {%4,%5,%6,%7}, {%8,%9}, {%10,%11,%12,%13};\n"
        : "=f"(d[0]), "=f"(d[1]), "=f"(d[2]), "=f"(d[3])
        : "r"(a[0]), "r"(a[1]), "r"(a[2]), "r"(a[3]),
          "r"(b[0]), "r"(b[1]),
          "f"(c[0]), "f"(c[1]), "f"(c[2]), "f"(c[3]));
}

// ---------------- GEMM ----------------
// smem (u32), per matrix: [buf(2)][kg(2)][row(128)][8 words]
// kg word layout per row: w0=(h0,h1) w1=(h8,h9) w2=(h2,h3) w3=(h10,h11)
//                         w4=(h4,h5) w5=(h12,h13) w6=(h6,h7) w7=(h14,h15)
__global__ __launch_bounds__(512, 1) void gemm_tc_kernel(
    const float* __restrict__ x, const float* __restrict__ W,
    const int* __restrict__ subj, const float* __restrict__ gain,
    float* __restrict__ emb)
{
    __shared__ uint32_t smA[2 * 2 * 128 * 8];
    __shared__ uint32_t smB[2 * 2 * 128 * 8];

    const int tid  = threadIdx.x;
    const int wid  = tid >> 5;
    const int lane = tid & 31;
    const int g    = lane >> 2;   // 0..7
    const int tg   = lane & 3;    // 0..3
    const int wm   = wid >> 2;    // 0..3 : 32-row warp tile
    const int wn   = wid & 3;     // 0..3 : 32-col warp tile

    const int row0 = blockIdx.x * BM;
    const int n0   = blockIdx.y * BN;

    // loaders: every thread loads A row (tid>>2) AND B row (tid>>2),
    // lane-quarter q = tid&3 covers floats [q*8, q*8+8) of the 32-float stage
    const int lrow = tid >> 2;          // 0..127
    const int q    = tid & 3;
    const int kg_l = q >> 1;            // which kg (0/1)
    const int half = q & 1;             // 0: h0..h7, 1: h8..h15
    const int kofs = q * 8;             // float offset within stage

    const float* srcA;
    {
        int ar = row0 + lrow;
        srcA = x + (size_t)(ar / PP) * TT + (ar % PP) * STRD + kofs;
    }
    const float* srcB = W + (size_t)(n0 + lrow) * PL + kofs;

    // store dst (word index within a kg tile of 1024 words)
    const int doff = kg_l * 1024 + lrow * 8 + half;

    float acc[2][4][4];
    #pragma unroll
    for (int mt = 0; mt < 2; ++mt)
        #pragma unroll
        for (int nt = 0; nt < 4; ++nt)
            #pragma unroll
            for (int qq = 0; qq < 4; ++qq) acc[mt][nt][qq] = 0.f;

    float4 va[2], vb[2];

    // prefetch stage 0
    #pragma unroll
    for (int j = 0; j < 2; ++j) {
        int k = kofs + j * 4;
        va[j] = (k < PL) ? *(const float4*)(srcA + j * 4) : make_float4(0.f,0.f,0.f,0.f);
        vb[j] = (k < PL) ? *(const float4*)(srcB + j * 4) : make_float4(0.f,0.f,0.f,0.f);
    }

    #pragma unroll 1
    for (int s = 0; s < NSTAGE; ++s) {
        const int buf = (s & 1) * 2048;
        // store current stage (pack fp32 -> fp16x2, permuted even/odd words)
        {
            const float* fa = (const float*)va;
            const float* fb = (const float*)vb;
            uint32_t* da = smA + buf + doff;
            uint32_t* db = smB + buf + doff;
            #pragma unroll
            for (int j = 0; j < 4; ++j) {
                da[2 * j] = packh2(fa[2 * j], fa[2 * j + 1]);
                db[2 * j] = packh2(fb[2 * j], fb[2 * j + 1]);
            }
        }
        __syncthreads();

        // prefetch next stage
        if (s + 1 < NSTAGE) {
            const int kb = (s + 1) * KSTG;
            #pragma unroll
            for (int j = 0; j < 2; ++j) {
                int rel = kb + j * 4;
                int k = kofs + rel;
                va[j] = (k < PL) ? *(const float4*)(srcA + rel) : make_float4(0.f,0.f,0.f,0.f);
                vb[j] = (k < PL) ? *(const float4*)(srcB + rel) : make_float4(0.f,0.f,0.f,0.f);
            }
        }

        // compute: kg pair (skip the all-zero kg 13 at s==6)
        #pragma unroll
        for (int kg = 0; kg < 2; ++kg) {
            if (s == NSTAGE - 1 && kg == 1) break;
            const uint32_t* ab = smA + buf + kg * 1024;
            const uint32_t* bb = smB + buf + kg * 1024;
            uint32_t af[2][4];
            #pragma unroll
            for (int mt = 0; mt < 2; ++mt) {
                int m = wm * 32 + mt * 16 + g;
                uint2 lo = *(const uint2*)(ab + m * 8 + tg * 2);
                uint2 hi = *(const uint2*)(ab + (m + 8) * 8 + tg * 2);
                af[mt][0] = lo.x; af[mt][1] = hi.x;
                af[mt][2] = lo.y; af[mt][3] = hi.y;
            }
            uint32_t bf[4][2];
            #pragma unroll
            for (int nt = 0; nt < 4; ++nt) {
                int n = wn * 32 + nt * 8 + g;
                uint2 bv = *(const uint2*)(bb + n * 8 + tg * 2);
                bf[nt][0] = bv.x; bf[nt][1] = bv.y;
            }
            #pragma unroll
            for (int mt = 0; mt < 2; ++mt)
                #pragma unroll
                for (int nt = 0; nt < 4; ++nt)
                    mma_f16_k16(acc[mt][nt], af[mt], bf[nt], acc[mt][nt]);
        }
        __syncthreads();
    }

    // epilogue: hoisted invariants + float2 loads
    const int dbase = n0 + wn * 32 + 2 * tg;
    float2 ws[4];
    #pragma unroll
    for (int nt = 0; nt < 4; ++nt)
        ws[nt] = *(const float2*)&g_wsum[dbase + nt * 8];

    #pragma unroll
    for (int mt = 0; mt < 2; ++mt) {
        #pragma unroll
        for (int h = 0; h < 2; ++h) {
            int r = row0 + wm * 32 + mt * 16 + g + h * 8;
            float mv = g_mean[r], iv = g_inv[r];
            int rp = r % PP;
            int sid = subj[(r / PP) >> 6];
            const float* gnrow = gain + (size_t)sid * EE;
            const float* perow = g_pe2 + (size_t)rp * EE;
            float* orow = emb + (size_t)r * EE;
            float miv = mv * iv;
            #pragma unroll
            for (int nt = 0; nt < 4; ++nt) {
                int d = dbase + nt * 8;
                float2 pv = *(const float2*)&perow[d];
                float2 gv = *(const float2*)&gnrow[d];
                float c0 = acc[mt][nt][h * 2 + 0];
                float c1 = acc[mt][nt][h * 2 + 1];
                float v0 = (iv * c0 - miv * ws[nt].x + pv.x) * gv.x;
                float v1 = (iv * c1 - miv * ws[nt].y + pv.y) * gv.y;
                *(float2*)&orow[d] = make_float2(v0, v1);
            }
        }
    }
}

// ---------------- JAX threefry2x32, partitionable mode ----------------
__device__ __forceinline__ void threefry(uint32_t k0, uint32_t k1,
                                         uint32_t x0, uint32_t x1,
                                         uint32_t& o0, uint32_t& o1) {
    uint32_t ks2 = k0 ^ k1 ^ 0x1BD11BDAu;
    x0 += k0; x1 += k1;
#define TF_RND(r) { x0 += x1; x1 = (x1 << r) | (x1 >> (32 - r)); x1 ^= x0; }
    TF_RND(13) TF_RND(15) TF_RND(26) TF_RND(6)  x0 += k1;  x1 += ks2 + 1u;
    TF_RND(17) TF_RND(29) TF_RND(16) TF_RND(24) x0 += ks2; x1 += k0 + 2u;
    TF_RND(13) TF_RND(15) TF_RND(26) TF_RND(6)  x0 += k0;  x1 += k1 + 3u;
    TF_RND(17) TF_RND(29) TF_RND(16) TF_RND(24) x0 += k1;  x1 += ks2 + 4u;
    TF_RND(13) TF_RND(15) TF_RND(26) TF_RND(6)  x0 += ks2; x1 += k0 + 5u;
#undef TF_RND
    o0 = x0; o1 = x1;
}

__device__ __forceinline__ uint32_t prf32(uint32_t k0, uint32_t k1, uint32_t i) {
    uint32_t o0, o1;
    threefry(k0, k1, 0u, i, o0, o1);
    return o0 ^ o1;
}

__device__ __forceinline__ float u01(uint32_t bits) {
    return __uint_as_float((bits >> 9) | 0x3f800000u) - 1.0f;
}

__global__ void mask_kernel(float* __restrict__ mout) {
    int row = blockIdx.x * blockDim.x + threadIdx.x;
    if (row >= BB * CC) return;
    uint32_t k1a, k1b, k2a, k2b;
    threefry(0u, 42u, 0u, 0u, k1a, k1b);
    threefry(0u, 42u, 0u, 1u, k2a, k2b);

    float r0 = u01(prf32(k2a, k2b, (uint32_t)(row * 3 + 0)));
    float r1 = u01(prf32(k2a, k2b, (uint32_t)(row * 3 + 1)));
    float r2 = u01(prf32(k2a, k2b, (uint32_t)(row * 3 + 2)));

    bool m[PP];
    #pragma unroll
    for (int j = 0; j < PP; ++j)
        m[j] = u01(prf32(k1a, k1b, (uint32_t)(row * PP + j))) < 0.1f;

    if (r0 < 0.5f)  { for (int j = PP - 1; j >= 1; --j) m[j] = m[j] | m[j - 1]; }
    if (r1 < 0.5f)  { for (int j = 0; j < PP - 1; ++j) m[j] = m[j] | m[j + 1]; }
    if (r2 < 0.25f) { for (int j = 0; j < PP - 1; ++j) m[j] = m[j] | m[j + 1]; }

    float* dst = mout + (size_t)row * PP;
    #pragma unroll
    for (int j = 0; j < PP; ++j) dst[j] = m[j] ? 1.0f : 0.0f;
}

// ---------------- launch ----------------
extern "C" void kernel_launch(void* const* d_in, const int* in_sizes, int n_in,
                              void* d_out, int out_size) {
    const float* x    = (const float*)d_in[0];
    const int*   subj = (const int*)  d_in[1];
    const float* W    = (const float*)d_in[2];
    const float* bias = (const float*)d_in[3];
    const float* pos  = (const float*)d_in[4];
    const float* gain = (const float*)d_in[5];

    float* out      = (float*)d_out;
    float* emb      = out;                               // 77824*512
    float* patches  = emb + (size_t)NROWS * EE;          // 77824*200
    float* mfloat   = patches + (size_t)NROWS * PL;      // 77824
    float* mean_out = mfloat + NROWS;                    // 77824
    float* std_out  = mean_out + NROWS;                  // 77824

    wsum_kernel<<<2, 256>>>(W);
    pe2_kernel<<<(PP * EE) / 256, 256>>>(bias, pos);
    stats_kernel<<<NROWS / 8, 256>>>(x, patches, mean_out, std_out);
    mask_kernel<<<(BB * CC) / 256, 256>>>(mfloat);
    dim3 g(NROWS / BM, EE / BN);
    gemm_tc_kernel<<<g, 512>>>(x, W, subj, gain, emb);
}

// round 12
// speedup vs baseline: 1.4534x; 1.0366x over previous
#include <cuda_runtime.h>
#include <cuda_fp16.h>
#include <cstdint>

// Problem constants
#define BB 64
#define CC 64
#define TT 2000
#define PL 200
#define STRD 100
#define EE 512
#define PP 19
#define NROWS (BB*CC*PP)   // 77824
#define EPSV 1e-5f

// GEMM tiling: 128M x 128N per CTA, 16 warps of 32x32, fp16 k16 MMA
#define BM 128
#define BN 128
#define KSTG 32        // floats per stage = 2 kg of 16
#define NSTAGE 7       // 224 padded K (13 real kg)
#define EPI_PITCH 132  // padded fp32 row pitch for epilogue staging

// Scratch
__device__ float g_mean[NROWS];
__device__ float g_inv[NROWS];
__device__ float g_wsum[EE];
__device__ float g_pe2[PP * EE];   // bias[d] + pos[p][d]

// ---------------- prep: wsum + pe2 fused ----------------
__global__ void prep_kernel(const float* __restrict__ W,
                            const float* __restrict__ bias,
                            const float* __restrict__ pos) {
    int b = blockIdx.x;
    if (b < 38) {                      // pe2: 38*256 = 9728 = PP*EE
        int i = b * 256 + threadIdx.x;
        g_pe2[i] = pos[i] + bias[i & (EE - 1)];
    } else {                           // wsum: 2*256 = 512
        int d = (b - 38) * 256 + threadIdx.x;
        const float* wr = W + (size_t)d * PL;
        float s = 0.f;
        #pragma unroll 8
        for (int l = 0; l < PL; ++l) s += wr[l];
        g_wsum[d] = s;
    }
}

// ---------------- stats + patches copy ----------------
__global__ void stats_kernel(const float* __restrict__ x,
                             float* __restrict__ patches,
                             float* __restrict__ mean_out,
                             float* __restrict__ std_out) {
    int warp = (blockIdx.x * blockDim.x + threadIdx.x) >> 5;
    int lane = threadIdx.x & 31;
    if (warp >= NROWS) return;
    int bc = warp / PP;
    int p  = warp % PP;
    const float* src = x + (size_t)bc * TT + p * STRD;
    float* dst = patches + (size_t)warp * PL;

    float s = 0.f, s2 = 0.f;
    #pragma unroll
    for (int i = 0; i < 7; ++i) {
        int l = lane + i * 32;
        if (l < PL) {
            float v = src[l];
            s += v; s2 += v * v;
            dst[l] = v;
        }
    }
    #pragma unroll
    for (int off = 16; off; off >>= 1) {
        s  += __shfl_xor_sync(0xffffffffu, s,  off);
        s2 += __shfl_xor_sync(0xffffffffu, s2, off);
    }
    if (lane == 0) {
        float mean = s * (1.f / PL);
        float var  = (s2 - s * mean) * (1.f / (PL - 1));
        float sd   = sqrtf(fmaxf(var, 0.f));
        mean_out[warp] = mean;
        std_out[warp]  = sd;
        g_mean[warp] = mean;
        g_inv[warp]  = 1.f / (sd + EPSV);
    }
}

// ---------------- fp16 mma helpers ----------------
__device__ __forceinline__ uint32_t packh2(float lo, float hi) {
    __half2 h = __floats2half2_rn(lo, hi);
    return *(uint32_t*)&h;
}

__device__ __forceinline__ void mma_f16_k16(float* d, const uint32_t* a,
                                            const uint32_t* b, const float* c) {
    asm volatile(
        "mma.sync.aligned.m16n8k16.row.col.f32.f16.f16.f32 "
        "{%0,%1,%2,%3}, {%4,%5,%6,%7}, {%8,%9}, {%10,%11,%12,%13};\n"
        : "=f"(d[0]), "=f"(d[1]), "=f"(d[2]), "=f"(d[3])
        : "r"(a[0]), "r"(a[1]), "r"(a[2]), "r"(a[3]),
          "r"(b[0]), "r"(b[1]),
          "f"(c[0]), "f"(c[1]), "f"(c[2]), "f"(c[3]));
}

// ---------------- GEMM ----------------
// smem (u32), per matrix: [buf(2)][kg(2)][row(128)][8 words]
// kg word layout per row: even words = (h0,h1)(h2,h3)(h4,h5)(h6,h7) at w0,w2,w4,w6
//                         odd  words = (h8,h9)(h10,h11)(h12,h13)(h14,h15) at w1,w3,w5,w7
__global__ __launch_bounds__(512, 1) void gemm_tc_kernel(
    const float* __restrict__ x, const float* __restrict__ W,
    const int* __restrict__ subj, const float* __restrict__ gain,
    float* __restrict__ emb)
{
    extern __shared__ uint32_t sm[];
    uint32_t* smA = sm;           // 8192 u32 (2 buf x 2 kg x 128 x 8)
    uint32_t* smB = sm + 8192;    // 8192 u32
    float* epi = (float*)sm;      // 128 x 132 fp32 (reused after mainloop)

    const int tid  = threadIdx.x;
    const int wid  = tid >> 5;
    const int lane = tid & 31;
    const int g    = lane >> 2;   // 0..7
    const int tg   = lane & 3;    // 0..3
    const int wm   = wid >> 2;    // 0..3 : 32-row warp tile
    const int wn   = wid & 3;     // 0..3 : 32-col warp tile

    const int row0 = blockIdx.x * BM;
    const int n0   = blockIdx.y * BN;

    // loaders: 8 lanes per row x 16B -> warp covers 4 rows x 128B contiguous
    const int lrow8 = tid >> 3;    // 0..63 ; covers rows lrow8 and lrow8+64
    const int lq    = tid & 7;     // k float offset = lq*4
    const int kofs  = lq * 4;
    const int kg_l  = lq >> 2;                 // kg of this 4-float chunk
    const int ko    = (lq & 3) * 4;            // float offset within kg
    const int w0    = (ko < 8) ? ko : (ko - 7);  // first word index (pair-permuted)

    const float* srcA0;
    const float* srcA1;
    {
        int ar0 = row0 + lrow8;
        int ar1 = row0 + lrow8 + 64;
        srcA0 = x + (size_t)(ar0 / PP) * TT + (ar0 % PP) * STRD + kofs;
        srcA1 = x + (size_t)(ar1 / PP) * TT + (ar1 % PP) * STRD + kofs;
    }
    const float* srcB0 = W + (size_t)(n0 + lrow8) * PL + kofs;
    const float* srcB1 = W + (size_t)(n0 + lrow8 + 64) * PL + kofs;

    float acc[2][4][4];
    #pragma unroll
    for (int mt = 0; mt < 2; ++mt)
        #pragma unroll
        for (int nt = 0; nt < 4; ++nt)
            #pragma unroll
            for (int qq = 0; qq < 4; ++qq) acc[mt][nt][qq] = 0.f;

    float4 va0, va1, vb0, vb1;

    // prefetch stage 0 (kofs < PL always for s=0)
    va0 = *(const float4*)srcA0;
    va1 = *(const float4*)srcA1;
    vb0 = *(const float4*)srcB0;
    vb1 = *(const float4*)srcB1;

    #pragma unroll 1
    for (int s = 0; s < NSTAGE; ++s) {
        const int buf = (s & 1) * 4096;
        // store current stage: 2 STS.32 per (row, matrix)
        {
            uint32_t* da0 = smA + buf + kg_l * 1024 + lrow8 * 8 + w0;
            uint32_t* da1 = smA + buf + kg_l * 1024 + (lrow8 + 64) * 8 + w0;
            uint32_t* db0 = smB + buf + kg_l * 1024 + lrow8 * 8 + w0;
            uint32_t* db1 = smB + buf + kg_l * 1024 + (lrow8 + 64) * 8 + w0;
            da0[0] = packh2(va0.x, va0.y); da0[2] = packh2(va0.z, va0.w);
            da1[0] = packh2(va1.x, va1.y); da1[2] = packh2(va1.z, va1.w);
            db0[0] = packh2(vb0.x, vb0.y); db0[2] = packh2(vb0.z, vb0.w);
            db1[0] = packh2(vb1.x, vb1.y); db1[2] = packh2(vb1.z, vb1.w);
        }
        __syncthreads();

        // prefetch next stage
        if (s + 1 < NSTAGE) {
            const int rel = (s + 1) * KSTG;
            const bool ok = (rel + kofs) < PL;
            va0 = ok ? *(const float4*)(srcA0 + rel) : make_float4(0.f,0.f,0.f,0.f);
            va1 = ok ? *(const float4*)(srcA1 + rel) : make_float4(0.f,0.f,0.f,0.f);
            vb0 = ok ? *(const float4*)(srcB0 + rel) : make_float4(0.f,0.f,0.f,0.f);
            vb1 = ok ? *(const float4*)(srcB1 + rel) : make_float4(0.f,0.f,0.f,0.f);
        }

        // compute: kg pair (skip the all-zero kg 13 at s==6)
        #pragma unroll
        for (int kg = 0; kg < 2; ++kg) {
            if (s == NSTAGE - 1 && kg == 1) break;
            const uint32_t* ab = smA + buf + kg * 1024;
            const uint32_t* bb = smB + buf + kg * 1024;
            uint32_t af[2][4];
            #pragma unroll
            for (int mt = 0; mt < 2; ++mt) {
                int m = wm * 32 + mt * 16 + g;
                uint2 lo = *(const uint2*)(ab + m * 8 + tg * 2);
                uint2 hi = *(const uint2*)(ab + (m + 8) * 8 + tg * 2);
                af[mt][0] = lo.x; af[mt][1] = hi.x;
                af[mt][2] = lo.y; af[mt][3] = hi.y;
            }
            uint32_t bf[4][2];
            #pragma unroll
            for (int nt = 0; nt < 4; ++nt) {
                int n = wn * 32 + nt * 8 + g;
                uint2 bv = *(const uint2*)(bb + n * 8 + tg * 2);
                bf[nt][0] = bv.x; bf[nt][1] = bv.y;
            }
            #pragma unroll
            for (int mt = 0; mt < 2; ++mt)
                #pragma unroll
                for (int nt = 0; nt < 4; ++nt)
                    mma_f16_k16(acc[mt][nt], af[mt], bf[nt], acc[mt][nt]);
        }
        __syncthreads();
    }

    // ---- staged epilogue ----
    // 1) raw accumulators -> padded smem tile (conflict-free STS.64)
    {
        const int dloc = wn * 32 + 2 * tg;
        #pragma unroll
        for (int mt = 0; mt < 2; ++mt) {
            #pragma unroll
            for (int h = 0; h < 2; ++h) {
                int rloc = wm * 32 + mt * 16 + g + h * 8;
                float* erow = epi + rloc * EPI_PITCH + dloc;
                #pragma unroll
                for (int nt = 0; nt < 4; ++nt)
                    *(float2*)(erow + nt * 8) =
                        make_float2(acc[mt][nt][h * 2 + 0], acc[mt][nt][h * 2 + 1]);
            }
        }
    }
    __syncthreads();

    // 2) coalesced fused copy-out: one warp = one full row pass
    #pragma unroll 1
    for (int it = 0; it < 8; ++it) {
        int fid = it * 512 + tid;
        int row = fid >> 5;            // 0..127
        int c4  = (fid & 31) * 4;      // 0..124
        int r   = row0 + row;
        float mv = g_mean[r], iv = g_inv[r];
        float miv = mv * iv;
        int rp  = r % PP;
        int sid = subj[(r / PP) >> 6];
        int d   = n0 + c4;

        float4 a  = *(float4*)&epi[row * EPI_PITCH + c4];
        float4 w4 = *(const float4*)&g_wsum[d];
        float4 p4 = *(const float4*)&g_pe2[rp * EE + d];
        float4 g4 = *(const float4*)&gain[(size_t)sid * EE + d];
        float4 o;
        o.x = (iv * a.x - miv * w4.x + p4.x) * g4.x;
        o.y = (iv * a.y - miv * w4.y + p4.y) * g4.y;
        o.z = (iv * a.z - miv * w4.z + p4.z) * g4.z;
        o.w = (iv * a.w - miv * w4.w + p4.w) * g4.w;
        *(float4*)&emb[(size_t)r * EE + d] = o;
    }
}

// ---------------- JAX threefry2x32, partitionable mode ----------------
__device__ __forceinline__ void threefry(uint32_t k0, uint32_t k1,
                                         uint32_t x0, uint32_t x1,
                                         uint32_t& o0, uint32_t& o1) {
    uint32_t ks2 = k0 ^ k1 ^ 0x1BD11BDAu;
    x0 += k0; x1 += k1;
#define TF_RND(r) { x0 += x1; x1 = (x1 << r) | (x1 >> (32 - r)); x1 ^= x0; }
    TF_RND(13) TF_RND(15) TF_RND(26) TF_RND(6)  x0 += k1;  x1 += ks2 + 1u;
    TF_RND(17) TF_RND(29) TF_RND(16) TF_RND(24) x0 += ks2; x1 += k0 + 2u;
    TF_RND(13) TF_RND(15) TF_RND(26) TF_RND(6)  x0 += k0;  x1 += k1 + 3u;
    TF_RND(17) TF_RND(29) TF_RND(16) TF_RND(24) x0 += k1;  x1 += ks2 + 4u;
    TF_RND(13) TF_RND(15) TF_RND(26) TF_RND(6)  x0 += ks2; x1 += k0 + 5u;
#undef TF_RND
    o0 = x0; o1 = x1;
}

__device__ __forceinline__ uint32_t prf32(uint32_t k0, uint32_t k1, uint32_t i) {
    uint32_t o0, o1;
    threefry(k0, k1, 0u, i, o0, o1);
    return o0 ^ o1;
}

__device__ __forceinline__ float u01(uint32_t bits) {
    return __uint_as_float((bits >> 9) | 0x3f800000u) - 1.0f;
}

__global__ void mask_kernel(float* __restrict__ mout) {
    int row = blockIdx.x * blockDim.x + threadIdx.x;
    if (row >= BB * CC) return;
    uint32_t k1a, k1b, k2a, k2b;
    threefry(0u, 42u, 0u, 0u, k1a, k1b);
    threefry(0u, 42u, 0u, 1u, k2a, k2b);

    float r0 = u01(prf32(k2a, k2b, (uint32_t)(row * 3 + 0)));
    float r1 = u01(prf32(k2a, k2b, (uint32_t)(row * 3 + 1)));
    float r2 = u01(prf32(k2a, k2b, (uint32_t)(row * 3 + 2)));

    bool m[PP];
    #pragma unroll
    for (int j = 0; j < PP; ++j)
        m[j] = u01(prf32(k1a, k1b, (uint32_t)(row * PP + j))) < 0.1f;

    if (r0 < 0.5f)  { for (int j = PP - 1; j >= 1; --j) m[j] = m[j] | m[j - 1]; }
    if (r1 < 0.5f)  { for (int j = 0; j < PP - 1; ++j) m[j] = m[j] | m[j + 1]; }
    if (r2 < 0.25f) { for (int j = 0; j < PP - 1; ++j) m[j] = m[j] | m[j + 1]; }

    float* dst = mout + (size_t)row * PP;
    #pragma unroll
    for (int j = 0; j < PP; ++j) dst[j] = m[j] ? 1.0f : 0.0f;
}

// ---------------- launch ----------------
extern "C" void kernel_launch(void* const* d_in, const int* in_sizes, int n_in,
                              void* d_out, int out_size) {
    const float* x    = (const float*)d_in[0];
    const int*   subj = (const int*)  d_in[1];
    const float* W    = (const float*)d_in[2];
    const float* bias = (const float*)d_in[3];
    const float* pos  = (const float*)d_in[4];
    const float* gain = (const float*)d_in[5];

    float* out      = (float*)d_out;
    float* emb      = out;                               // 77824*512
    float* patches  = emb + (size_t)NROWS * EE;          // 77824*200
    float* mfloat   = patches + (size_t)NROWS * PL;      // 77824
    float* mean_out = mfloat + NROWS;                    // 77824
    float* std_out  = mean_out + NROWS;                  // 77824

    const int smem_bytes = BM * EPI_PITCH * 4;           // 67584 > 65536 mainloop
    cudaFuncSetAttribute(gemm_tc_kernel,
                         cudaFuncAttributeMaxDynamicSharedMemorySize, smem_bytes);

    prep_kernel<<<40, 256>>>(W, bias, pos);
    stats_kernel<<<NROWS / 8, 256>>>(x, patches, mean_out, std_out);
    mask_kernel<<<(BB * CC) / 256, 256>>>(mfloat);
    dim3 g(NROWS / BM, EE / BN);
    gemm_tc_kernel<<<g, 512, smem_bytes>>>(x, W, subj, gain, emb);
}